// round 15
// baseline (speedup 1.0000x reference)
#include <cuda_runtime.h>
#include <cuda_fp16.h>
#include <math.h>
#include <stdint.h>

#define B_  32
#define T_  2048
#define D_  1024
#define M_  (B_ * T_)
#define KS_  4

// ---------------- scratch (static device globals; no allocation) ----------------
// chunk-major, pre-swizzled: block (c, m) at (c*M_ + m)*32 halves (64B), inner
// 16B-unit u stored at position (u ^ ((m>>1)&3))&3.
__device__ __half g_va[(size_t)M_ * D_];     // 128 MB values fp16
__device__ __half g_wt[(size_t)D_ * D_];     // 2 MB  Ws^T fp16, same block layout (n)
__device__ float g_qpart[KS_ * B_ * D_];
__device__ float g_spart[4 * M_];            // per-n-quarter score partials

// ---------------- PTX helpers ----------------
__device__ __forceinline__ uint32_t smem_u32(const void* p) {
    uint32_t a;
    asm("{ .reg .u64 t; cvta.to.shared.u64 t, %1; cvt.u32.u64 %0, t; }" : "=r"(a) : "l"(p));
    return a;
}
__device__ __forceinline__ void ldsm4(uint32_t* r, uint32_t addr) {
    asm volatile("ldmatrix.sync.aligned.m8n8.x4.shared.b16 {%0,%1,%2,%3}, [%4];"
        : "=r"(r[0]), "=r"(r[1]), "=r"(r[2]), "=r"(r[3]) : "r"(addr));
}
__device__ __forceinline__ void mma_f32(float* d, const uint32_t* a, uint32_t b0, uint32_t b1) {
    asm("mma.sync.aligned.m16n8k16.row.col.f32.f16.f16.f32 "
        "{%0,%1,%2,%3}, {%4,%5,%6,%7}, {%8,%9}, {%0,%1,%2,%3};"
        : "+f"(d[0]), "+f"(d[1]), "+f"(d[2]), "+f"(d[3])
        : "r"(a[0]), "r"(a[1]), "r"(a[2]), "r"(a[3]), "r"(b0), "r"(b1));
}
#define MBAR_INIT(a, c) \
    asm volatile("mbarrier.init.shared.b64 [%0], %1;" :: "r"((uint32_t)(a)), "r"((uint32_t)(c)) : "memory")
#define MBAR_EXPECT_TX(a, n) \
    asm volatile("mbarrier.arrive.expect_tx.shared.b64 _, [%0], %1;" :: "r"((uint32_t)(a)), "r"((uint32_t)(n)) : "memory")
#define MBAR_WAIT(a, par) do { \
    uint32_t _m = (uint32_t)(a), _p = (uint32_t)(par), _d; \
    asm volatile("{\n\t.reg .pred p;\n\t" \
        "mbarrier.try_wait.parity.acquire.cta.shared::cta.b64 p, [%1], %2;\n\t" \
        "selp.b32 %0, 1, 0, p;\n\t}" : "=r"(_d) : "r"(_m), "r"(_p) : "memory"); \
    if (!_d) { \
        asm volatile("{\n\t.reg .pred P1;\n\t" \
            "WL_%=:\n\t" \
            "mbarrier.try_wait.parity.acquire.cta.shared::cta.b64 P1, [%0], %1, 0x989680;\n\t" \
            "@P1 bra.uni WD_%=;\n\t" \
            "bra.uni WL_%=;\n\t" \
            "WD_%=:\n\t}" :: "r"(_m), "r"(_p) : "memory"); \
    } \
} while (0)
__device__ __forceinline__ void bulk_cp(uint32_t dst, const void* src, uint32_t bytes, uint32_t mbar) {
    asm volatile("cp.async.bulk.shared::cta.global.mbarrier::complete_tx::bytes [%0], [%1], %2, [%3];"
        :: "r"(dst), "l"(src), "r"(bytes), "r"(mbar) : "memory");
}

// ============================================================================
// merged prep: conv_values (32768 blocks) | conv_ws (1024) | qproj (512)
// ============================================================================
#define NB_CV 32768
#define NB_CW 1024
#define NB_QP 512
__global__ void prep_kernel(const float* __restrict__ v,
                            const float* __restrict__ Ws,
                            const float* __restrict__ query,
                            const float* __restrict__ Wh,
                            const float* __restrict__ bh,
                            const float* __restrict__ bs,
                            const float* __restrict__ bc) {
    __shared__ float tile[32][33];
    const int bid = blockIdx.x;
    const int tid = threadIdx.x;

    if (bid < NB_CV) {
        // ---- conv_values: f32 [m][k] -> fp16 chunk-major pre-swizzled ----
        size_t t = (size_t)bid * 256 + tid;
        int u = (int)(t & 3);
        int m = (int)((t >> 2) & (M_ - 1));
        int c = (int)(t >> 18);
        const float4* src = (const float4*)(v + (size_t)m * D_ + c * 32 + u * 8);
        float4 x0 = src[0], x1 = src[1];
        __half h[8];
        h[0] = __float2half_rn(x0.x); h[1] = __float2half_rn(x0.y);
        h[2] = __float2half_rn(x0.z); h[3] = __float2half_rn(x0.w);
        h[4] = __float2half_rn(x1.x); h[5] = __float2half_rn(x1.y);
        h[6] = __float2half_rn(x1.z); h[7] = __float2half_rn(x1.w);
        int sw = (u ^ ((m >> 1) & 3)) & 3;
        *(uint4*)(g_va + ((size_t)c * M_ + m) * 32 + sw * 8) = *(uint4*)h;
    } else if (bid < NB_CV + NB_CW) {
        // ---- conv_ws: Ws [k][n] -> transposed fp16 chunk-major swizzled ----
        int cw = bid - NB_CV;
        const int n0 = (cw & 31) * 32, c = cw >> 5;
        const int tx = tid & 31, ty = tid >> 5;
        #pragma unroll
        for (int i = 0; i < 32; i += 8)
            tile[ty + i][tx] = Ws[(size_t)(c * 32 + ty + i) * D_ + n0 + tx];
        __syncthreads();
        if (tid < 128) {
            int nl = tid >> 2, u = tid & 3;
            __half h[8];
            #pragma unroll
            for (int j = 0; j < 8; ++j)
                h[j] = __float2half_rn(tile[u * 8 + j][nl]);
            int sw = (u ^ ((nl >> 1) & 3)) & 3;
            *(uint4*)(g_wt + ((size_t)c * D_ + n0 + nl) * 32 + sw * 8) = *(uint4*)h;
        }
    } else {
        // ---- qproj partials (k-split x4) ----
        int kbid = bid - NB_CV - NB_CW;
        int ks = kbid >> 7;
        int g  = (kbid & 127) * 256 + tid;
        int u = g & (D_ - 1);
        int b = g >> 10;
        float acc = (ks == 0) ? (bh[u] + bs[u] + bc[u]) : 0.0f;
        const float* q = query + (size_t)b * D_;
        int kbeg = ks * (D_ / KS_), kend = kbeg + D_ / KS_;
        #pragma unroll 8
        for (int k = kbeg; k < kend; ++k)
            acc = fmaf(q[k], Wh[(size_t)k * D_ + u], acc);
        g_qpart[(size_t)ks * B_ * D_ + g] = acc;
    }
}

// ============================================================================
// score GEMM: CTA = 128M x 256N quarter; grid (4 n-quarters, 512 m-blocks).
// 8 warps, warp tile 64x64. Pure fp16 HMMA, fp32 accumulate.
// smem fill via cp.async.bulk (A 8KB + B 16KB per chunk) + mbarrier.
// ============================================================================
#define BUF_B 24576                 // A 8K | B 16K
#define O_BH  8192
#define NSTAGE 3
#define MBAR_OFF (NSTAGE * BUF_B)   // 73728
#define EPI_OFF (MBAR_OFF + 64)
#define GEMM_SMEM (EPI_OFF + (256 * 3 + 128 + 512) * 4)

__global__ __launch_bounds__(256, 1)
void score_gemm_kernel(const float* __restrict__ prev_cov,
                       const float* __restrict__ Wc,
                       const float* __restrict__ Vw) {
    extern __shared__ char smem[];
    const uint32_t sb = smem_u32(smem);
    float* qb_s = (float*)(smem + EPI_OFF);          // 256
    float* wc_s = qb_s + 256;
    float* vw_s = qb_s + 512;
    float* pc_s = qb_s + 768;                        // 128
    float (*Red)[4] = (float(*)[4])(qb_s + 896);     // [128][4]

    const int tid  = threadIdx.x;
    const int wid  = tid >> 5;
    const int lane = tid & 31;
    const int wm   = (wid >> 2) * 64;                // 0 / 64
    const int wn   = (wid & 3) * 64;                 // 0..192

    const int nh  = blockIdx.x;                      // 0..3
    const int mb  = blockIdx.y;                      // 0..511
    const int m0  = mb * 128;
    const int b   = mb >> 4;
    const int tt0 = (mb & 15) * 128;

    if (tid == 0) {
        MBAR_INIT(sb + MBAR_OFF + 0,  1);
        MBAR_INIT(sb + MBAR_OFF + 8,  1);
        MBAR_INIT(sb + MBAR_OFF + 16, 1);
    }
    if (tid < 128) pc_s[tid] = prev_cov[(size_t)b * T_ + tt0 + tid];
    {
        int n = nh * 256 + tid;
        float q = g_qpart[(size_t)b * D_ + n]
                + g_qpart[(size_t)B_ * D_ + (size_t)b * D_ + n]
                + g_qpart[(size_t)2 * B_ * D_ + (size_t)b * D_ + n]
                + g_qpart[(size_t)3 * B_ * D_ + (size_t)b * D_ + n];
        qb_s[tid] = q;
        wc_s[tid] = Wc[n];
        vw_s[tid] = Vw[n];
    }
    __syncthreads();

    // ---- hoisted fragment addressing (kk=16 differs by ^0x20) ----
    const int lr  = (lane & 7) + (lane & 8);
    const uint32_t k8 = lane >> 4;                   // 0/1
    uint32_t aoff[4], boff[4];
    #pragma unroll
    for (int mf = 0; mf < 4; ++mf) {
        int r = wm + mf * 16 + lr;
        aoff[mf] = (uint32_t)(r << 6) + (((k8 ^ (r >> 1)) & 3) << 4);
    }
    #pragma unroll
    for (int p = 0; p < 4; ++p) {
        int n = wn + p * 16 + lr;
        boff[p] = (uint32_t)(n << 6) + (((k8 ^ (n >> 1)) & 3) << 4) + O_BH;
    }

    float acc[4][8][4];
    #pragma unroll
    for (int i = 0; i < 4; ++i)
        #pragma unroll
        for (int j = 0; j < 8; ++j)
            #pragma unroll
            for (int r = 0; r < 4; ++r) acc[i][j][r] = 0.0f;

    #define ISSUE_BULK(c) do {                                                 \
        if (tid == 0) {                                                        \
            int s_ = (c) % NSTAGE;                                             \
            uint32_t mb_ = sb + MBAR_OFF + s_ * 8;                             \
            uint32_t bb_ = sb + s_ * BUF_B;                                    \
            MBAR_EXPECT_TX(mb_, 24576u);                                       \
            bulk_cp(bb_,        g_va + ((size_t)(c) * M_ + m0) * 32,           \
                    8192u, mb_);                                               \
            bulk_cp(bb_ + O_BH, g_wt + ((size_t)(c) * D_ + nh * 256) * 32,     \
                    16384u, mb_);                                              \
        }                                                                      \
    } while (0)

    ISSUE_BULK(0);
    ISSUE_BULK(1);

    for (int c = 0; c < 32; ++c) {
        const int s = c % NSTAGE;
        MBAR_WAIT(sb + MBAR_OFF + s * 8, (uint32_t)((c / 3) & 1));
        __syncthreads();
        if (c + 2 < 32) ISSUE_BULK(c + 2);

        const uint32_t bb = sb + s * BUF_B;
        #pragma unroll
        for (int kk = 0; kk < 32; kk += 16) {
            const uint32_t xm = kk ? 0x20u : 0u;
            uint32_t af[4][4], bf[4][4];
            #pragma unroll
            for (int mf = 0; mf < 4; ++mf) ldsm4(af[mf], (bb + aoff[mf]) ^ xm);
            #pragma unroll
            for (int p = 0; p < 4; ++p)   ldsm4(bf[p], (bb + boff[p]) ^ xm);
            #pragma unroll
            for (int mf = 0; mf < 4; ++mf)
                #pragma unroll
                for (int p = 0; p < 4; ++p) {
                    mma_f32(acc[mf][2 * p],     af[mf], bf[p][0], bf[p][2]);
                    mma_f32(acc[mf][2 * p + 1], af[mf], bf[p][1], bf[p][3]);
                }
        }
    }

    // fused epilogue: tanh(act + qb + pc*Wc) * Vw, reduce over this n-quarter
    #pragma unroll
    for (int mf = 0; mf < 4; ++mf) {
        const int rA = wm + mf * 16 + (lane >> 2);
        const float pA = pc_s[rA], pB = pc_s[rA + 8];
        float sA = 0.f, sB = 0.f;
        #pragma unroll
        for (int nf = 0; nf < 8; ++nf) {
            int c0 = wn + nf * 8 + 2 * (lane & 3);
            int c1 = c0 + 1;
            sA += tanhf(acc[mf][nf][0] + qb_s[c0] + pA * wc_s[c0]) * vw_s[c0];
            sA += tanhf(acc[mf][nf][1] + qb_s[c1] + pA * wc_s[c1]) * vw_s[c1];
            sB += tanhf(acc[mf][nf][2] + qb_s[c0] + pB * wc_s[c0]) * vw_s[c0];
            sB += tanhf(acc[mf][nf][3] + qb_s[c1] + pB * wc_s[c1]) * vw_s[c1];
        }
        sA += __shfl_xor_sync(0xffffffff, sA, 1);
        sA += __shfl_xor_sync(0xffffffff, sA, 2);
        sB += __shfl_xor_sync(0xffffffff, sB, 1);
        sB += __shfl_xor_sync(0xffffffff, sB, 2);
        if ((lane & 3) == 0) {
            Red[rA][wid & 3]     = sA;
            Red[rA + 8][wid & 3] = sB;
        }
    }
    __syncthreads();
    if (tid < 128) {
        g_spart[(size_t)nh * M_ + m0 + tid] =
            Red[tid][0] + Red[tid][1] + Red[tid][2] + Red[tid][3];
    }
}

// ============================================================================
// softmax over T per batch; writes attention_weights + coverage
// ============================================================================
__global__ void softmax_kernel(const float* __restrict__ prev_cov,
                               const float* __restrict__ Vb,
                               float* __restrict__ out) {
    __shared__ float sc[T_];
    __shared__ float red[256];
    const int b = blockIdx.x;
    const int tid = threadIdx.x;
    const float vb = Vb[0];

    float lmax = -1e30f;
    for (int t = tid; t < T_; t += 256) {
        size_t i = (size_t)b * T_ + t;
        float s = g_spart[i] + g_spart[M_ + i] + g_spart[2 * (size_t)M_ + i]
                + g_spart[3 * (size_t)M_ + i] + vb;
        sc[t] = s;
        lmax = fmaxf(lmax, s);
    }
    red[tid] = lmax;
    __syncthreads();
    for (int st = 128; st > 0; st >>= 1) {
        if (tid < st) red[tid] = fmaxf(red[tid], red[tid + st]);
        __syncthreads();
    }
    const float mx = red[0];
    __syncthreads();

    float lsum = 0.0f;
    for (int t = tid; t < T_; t += 256) {
        float e = expf(sc[t] - mx);
        sc[t] = e;
        lsum += e;
    }
    red[tid] = lsum;
    __syncthreads();
    for (int st = 128; st > 0; st >>= 1) {
        if (tid < st) red[tid] += red[tid + st];
        __syncthreads();
    }
    const float inv = 1.0f / red[0];

    float* aw_out  = out + B_ * D_;
    float* cov_out = out + B_ * D_ + B_ * T_;
    const float* pc = prev_cov + (size_t)b * T_;
    for (int t = tid; t < T_; t += 256) {
        float a = sc[t] * inv;
        aw_out[(size_t)b * T_ + t]  = a;
        cov_out[(size_t)b * T_ + t] = a + pc[t];
    }
}

// ============================================================================
// context: grid (32 chunks, 32 b), 256 threads over T. Each thread reads its
// t's full 64B block of chunk c (warp = 2KB contiguous), scales by aw[t],
// accumulates 32 d in regs; warp butterfly + smem combine -> FINAL
// context[b][c*32..c*32+31]. No partial buffer, no reduce kernel.
// ============================================================================
__global__ void ctx_kernel(const float* __restrict__ aw, float* __restrict__ out) {
    __shared__ float red[8][33];
    const int c = blockIdx.x, b = blockIdx.y;
    const int tid = threadIdx.x;
    const int w = tid >> 5, lane = tid & 31;

    const __half* base = g_va + ((size_t)c * M_ + (size_t)b * T_) * 32;
    const float* ap = aw + (size_t)b * T_;

    float acc[32];
    #pragma unroll
    for (int e = 0; e < 32; ++e) acc[e] = 0.f;

    #pragma unroll 2
    for (int t = tid; t < T_; t += 256) {
        float a = ap[t];
        const uint4* blk = (const uint4*)(base + (size_t)t * 32);
        uint4 arr[4];
        arr[0] = blk[0]; arr[1] = blk[1]; arr[2] = blk[2]; arr[3] = blk[3];
        const int swv = (t >> 1) & 3;
        #pragma unroll
        for (int u = 0; u < 4; ++u) {
            uint4 raw = arr[u ^ swv];
            const __half2* hp = (const __half2*)&raw;
            #pragma unroll
            for (int q = 0; q < 4; ++q) {
                float2 f = __half22float2(hp[q]);
                acc[u * 8 + 2 * q]     = fmaf(a, f.x, acc[u * 8 + 2 * q]);
                acc[u * 8 + 2 * q + 1] = fmaf(a, f.y, acc[u * 8 + 2 * q + 1]);
            }
        }
    }

    // warp butterfly: all lanes end with warp-total for each e
    #pragma unroll
    for (int off = 16; off > 0; off >>= 1)
        #pragma unroll
        for (int e = 0; e < 32; ++e)
            acc[e] += __shfl_xor_sync(0xffffffff, acc[e], off);

    red[w][lane] = acc[lane];       // lane l stores element e=l of warp w
    __syncthreads();
    if (tid < 32) {
        float s = 0.f;
        #pragma unroll
        for (int ww = 0; ww < 8; ++ww) s += red[ww][tid];
        out[(size_t)b * D_ + c * 32 + tid] = s;
    }
}

// ============================================================================
extern "C" void kernel_launch(void* const* d_in, const int* in_sizes, int n_in,
                              void* d_out, int out_size) {
    const float* query    = (const float*)d_in[0];
    const float* values   = (const float*)d_in[1];
    const float* prev_cov = (const float*)d_in[2];
    const float* Wh       = (const float*)d_in[3];
    const float* bh       = (const float*)d_in[4];
    const float* Ws       = (const float*)d_in[5];
    const float* bs       = (const float*)d_in[6];
    const float* Wc       = (const float*)d_in[7];
    const float* bc       = (const float*)d_in[8];
    const float* Vw       = (const float*)d_in[9];
    const float* Vb       = (const float*)d_in[10];
    float* out = (float*)d_out;

    cudaFuncSetAttribute(score_gemm_kernel,
                         cudaFuncAttributeMaxDynamicSharedMemorySize, GEMM_SMEM);

    prep_kernel<<<NB_CV + NB_CW + NB_QP, 256>>>(values, Ws, query, Wh, bh, bs, bc);
    score_gemm_kernel<<<dim3(4, M_ / 128), 256, GEMM_SMEM>>>(prev_cov, Wc, Vw);
    softmax_kernel<<<B_, 256>>>(prev_cov, Vb, out);
    ctx_kernel<<<dim3(32, B_), 256>>>(out + B_ * D_, out);
}

// round 16
// speedup vs baseline: 1.0086x; 1.0086x over previous
#include <cuda_runtime.h>
#include <cuda_fp16.h>
#include <math.h>
#include <stdint.h>

#define B_  32
#define T_  2048
#define D_  1024
#define M_  (B_ * T_)
#define KS_  4

// ---------------- scratch (static device globals; no allocation) ----------------
// chunk-major, pre-swizzled: block (c, m) at (c*M_ + m)*32 halves (64B), inner
// 16B-unit u stored at position (u ^ ((m>>1)&3))&3.
__device__ __half g_va[(size_t)M_ * D_];     // 128 MB values fp16
__device__ __half g_wt[(size_t)D_ * D_];     // 2 MB  Ws^T fp16, same block layout (n)
__device__ float g_qpart[KS_ * B_ * D_];
__device__ float g_spart[4 * M_];            // per-n-quarter score partials

// ---------------- PTX helpers ----------------
__device__ __forceinline__ uint32_t smem_u32(const void* p) {
    uint32_t a;
    asm("{ .reg .u64 t; cvta.to.shared.u64 t, %1; cvt.u32.u64 %0, t; }" : "=r"(a) : "l"(p));
    return a;
}
__device__ __forceinline__ void ldsm4(uint32_t* r, uint32_t addr) {
    asm volatile("ldmatrix.sync.aligned.m8n8.x4.shared.b16 {%0,%1,%2,%3}, [%4];"
        : "=r"(r[0]), "=r"(r[1]), "=r"(r[2]), "=r"(r[3]) : "r"(addr));
}
__device__ __forceinline__ void mma_f32(float* d, const uint32_t* a, uint32_t b0, uint32_t b1) {
    asm("mma.sync.aligned.m16n8k16.row.col.f32.f16.f16.f32 "
        "{%0,%1,%2,%3}, {%4,%5,%6,%7}, {%8,%9}, {%0,%1,%2,%3};"
        : "+f"(d[0]), "+f"(d[1]), "+f"(d[2]), "+f"(d[3])
        : "r"(a[0]), "r"(a[1]), "r"(a[2]), "r"(a[3]), "r"(b0), "r"(b1));
}
#define MBAR_INIT(a, c) \
    asm volatile("mbarrier.init.shared.b64 [%0], %1;" :: "r"((uint32_t)(a)), "r"((uint32_t)(c)) : "memory")
#define MBAR_EXPECT_TX(a, n) \
    asm volatile("mbarrier.arrive.expect_tx.shared.b64 _, [%0], %1;" :: "r"((uint32_t)(a)), "r"((uint32_t)(n)) : "memory")
#define MBAR_WAIT(a, par) do { \
    uint32_t _m = (uint32_t)(a), _p = (uint32_t)(par), _d; \
    asm volatile("{\n\t.reg .pred p;\n\t" \
        "mbarrier.try_wait.parity.acquire.cta.shared::cta.b64 p, [%1], %2;\n\t" \
        "selp.b32 %0, 1, 0, p;\n\t}" : "=r"(_d) : "r"(_m), "r"(_p) : "memory"); \
    if (!_d) { \
        asm volatile("{\n\t.reg .pred P1;\n\t" \
            "WL_%=:\n\t" \
            "mbarrier.try_wait.parity.acquire.cta.shared::cta.b64 P1, [%0], %1, 0x989680;\n\t" \
            "@P1 bra.uni WD_%=;\n\t" \
            "bra.uni WL_%=;\n\t" \
            "WD_%=:\n\t}" :: "r"(_m), "r"(_p) : "memory"); \
    } \
} while (0)
__device__ __forceinline__ void bulk_cp(uint32_t dst, const void* src, uint32_t bytes, uint32_t mbar) {
    asm volatile("cp.async.bulk.shared::cta.global.mbarrier::complete_tx::bytes [%0], [%1], %2, [%3];"
        :: "r"(dst), "l"(src), "r"(bytes), "r"(mbar) : "memory");
}

// ============================================================================
// merged prep: conv_values (32768 blocks) | conv_ws (1024) | qproj (512)
// ============================================================================
#define NB_CV 32768
#define NB_CW 1024
#define NB_QP 512
__global__ void prep_kernel(const float* __restrict__ v,
                            const float* __restrict__ Ws,
                            const float* __restrict__ query,
                            const float* __restrict__ Wh,
                            const float* __restrict__ bh,
                            const float* __restrict__ bs,
                            const float* __restrict__ bc) {
    __shared__ float tile[32][33];
    const int bid = blockIdx.x;
    const int tid = threadIdx.x;

    if (bid < NB_CV) {
        // ---- conv_values: f32 [m][k] -> fp16 chunk-major pre-swizzled ----
        size_t t = (size_t)bid * 256 + tid;
        int u = (int)(t & 3);
        int m = (int)((t >> 2) & (M_ - 1));
        int c = (int)(t >> 18);
        const float4* src = (const float4*)(v + (size_t)m * D_ + c * 32 + u * 8);
        float4 x0 = src[0], x1 = src[1];
        __half h[8];
        h[0] = __float2half_rn(x0.x); h[1] = __float2half_rn(x0.y);
        h[2] = __float2half_rn(x0.z); h[3] = __float2half_rn(x0.w);
        h[4] = __float2half_rn(x1.x); h[5] = __float2half_rn(x1.y);
        h[6] = __float2half_rn(x1.z); h[7] = __float2half_rn(x1.w);
        int sw = (u ^ ((m >> 1) & 3)) & 3;
        *(uint4*)(g_va + ((size_t)c * M_ + m) * 32 + sw * 8) = *(uint4*)h;
    } else if (bid < NB_CV + NB_CW) {
        // ---- conv_ws: Ws [k][n] -> transposed fp16 chunk-major swizzled ----
        int cw = bid - NB_CV;
        const int n0 = (cw & 31) * 32, c = cw >> 5;
        const int tx = tid & 31, ty = tid >> 5;
        #pragma unroll
        for (int i = 0; i < 32; i += 8)
            tile[ty + i][tx] = Ws[(size_t)(c * 32 + ty + i) * D_ + n0 + tx];
        __syncthreads();
        if (tid < 128) {
            int nl = tid >> 2, u = tid & 3;
            __half h[8];
            #pragma unroll
            for (int j = 0; j < 8; ++j)
                h[j] = __float2half_rn(tile[u * 8 + j][nl]);
            int sw = (u ^ ((nl >> 1) & 3)) & 3;
            *(uint4*)(g_wt + ((size_t)c * D_ + n0 + nl) * 32 + sw * 8) = *(uint4*)h;
        }
    } else {
        // ---- qproj partials (k-split x4) ----
        int kbid = bid - NB_CV - NB_CW;
        int ks = kbid >> 7;
        int g  = (kbid & 127) * 256 + tid;
        int u = g & (D_ - 1);
        int b = g >> 10;
        float acc = (ks == 0) ? (bh[u] + bs[u] + bc[u]) : 0.0f;
        const float* q = query + (size_t)b * D_;
        int kbeg = ks * (D_ / KS_), kend = kbeg + D_ / KS_;
        #pragma unroll 8
        for (int k = kbeg; k < kend; ++k)
            acc = fmaf(q[k], Wh[(size_t)k * D_ + u], acc);
        g_qpart[(size_t)ks * B_ * D_ + g] = acc;
    }
}

// ============================================================================
// score GEMM: CTA = 128M x 256N quarter; grid (4 n-quarters, 512 m-blocks).
// 8 warps, warp tile 64x64. Pure fp16 HMMA, fp32 accumulate.
// smem fill via cp.async.bulk (A 8KB + B 16KB per chunk) + mbarrier.
// ============================================================================
#define BUF_B 24576                 // A 8K | B 16K
#define O_BH  8192
#define NSTAGE 3
#define MBAR_OFF (NSTAGE * BUF_B)   // 73728
#define EPI_OFF (MBAR_OFF + 64)
#define GEMM_SMEM (EPI_OFF + (256 * 3 + 128 + 512) * 4)

__global__ __launch_bounds__(256, 1)
void score_gemm_kernel(const float* __restrict__ prev_cov,
                       const float* __restrict__ Wc,
                       const float* __restrict__ Vw) {
    extern __shared__ char smem[];
    const uint32_t sb = smem_u32(smem);
    float* qb_s = (float*)(smem + EPI_OFF);          // 256
    float* wc_s = qb_s + 256;
    float* vw_s = qb_s + 512;
    float* pc_s = qb_s + 768;                        // 128
    float (*Red)[4] = (float(*)[4])(qb_s + 896);     // [128][4]

    const int tid  = threadIdx.x;
    const int wid  = tid >> 5;
    const int lane = tid & 31;
    const int wm   = (wid >> 2) * 64;                // 0 / 64
    const int wn   = (wid & 3) * 64;                 // 0..192

    const int nh  = blockIdx.x;                      // 0..3
    const int mb  = blockIdx.y;                      // 0..511
    const int m0  = mb * 128;
    const int b   = mb >> 4;
    const int tt0 = (mb & 15) * 128;

    if (tid == 0) {
        MBAR_INIT(sb + MBAR_OFF + 0,  1);
        MBAR_INIT(sb + MBAR_OFF + 8,  1);
        MBAR_INIT(sb + MBAR_OFF + 16, 1);
    }
    if (tid < 128) pc_s[tid] = prev_cov[(size_t)b * T_ + tt0 + tid];
    {
        int n = nh * 256 + tid;
        float q = g_qpart[(size_t)b * D_ + n]
                + g_qpart[(size_t)B_ * D_ + (size_t)b * D_ + n]
                + g_qpart[(size_t)2 * B_ * D_ + (size_t)b * D_ + n]
                + g_qpart[(size_t)3 * B_ * D_ + (size_t)b * D_ + n];
        qb_s[tid] = q;
        wc_s[tid] = Wc[n];
        vw_s[tid] = Vw[n];
    }
    __syncthreads();

    // ---- hoisted fragment addressing (kk=16 differs by ^0x20) ----
    const int lr  = (lane & 7) + (lane & 8);
    const uint32_t k8 = lane >> 4;                   // 0/1
    uint32_t aoff[4], boff[4];
    #pragma unroll
    for (int mf = 0; mf < 4; ++mf) {
        int r = wm + mf * 16 + lr;
        aoff[mf] = (uint32_t)(r << 6) + (((k8 ^ (r >> 1)) & 3) << 4);
    }
    #pragma unroll
    for (int p = 0; p < 4; ++p) {
        int n = wn + p * 16 + lr;
        boff[p] = (uint32_t)(n << 6) + (((k8 ^ (n >> 1)) & 3) << 4) + O_BH;
    }

    float acc[4][8][4];
    #pragma unroll
    for (int i = 0; i < 4; ++i)
        #pragma unroll
        for (int j = 0; j < 8; ++j)
            #pragma unroll
            for (int r = 0; r < 4; ++r) acc[i][j][r] = 0.0f;

    #define ISSUE_BULK(c) do {                                                 \
        if (tid == 0) {                                                        \
            int s_ = (c) % NSTAGE;                                             \
            uint32_t mb_ = sb + MBAR_OFF + s_ * 8;                             \
            uint32_t bb_ = sb + s_ * BUF_B;                                    \
            MBAR_EXPECT_TX(mb_, 24576u);                                       \
            bulk_cp(bb_,        g_va + ((size_t)(c) * M_ + m0) * 32,           \
                    8192u, mb_);                                               \
            bulk_cp(bb_ + O_BH, g_wt + ((size_t)(c) * D_ + nh * 256) * 32,     \
                    16384u, mb_);                                              \
        }                                                                      \
    } while (0)

    ISSUE_BULK(0);
    ISSUE_BULK(1);

    for (int c = 0; c < 32; ++c) {
        const int s = c % NSTAGE;
        MBAR_WAIT(sb + MBAR_OFF + s * 8, (uint32_t)((c / 3) & 1));
        __syncthreads();
        if (c + 2 < 32) ISSUE_BULK(c + 2);

        const uint32_t bb = sb + s * BUF_B;
        #pragma unroll
        for (int kk = 0; kk < 32; kk += 16) {
            const uint32_t xm = kk ? 0x20u : 0u;
            uint32_t af[4][4], bf[4][4];
            #pragma unroll
            for (int mf = 0; mf < 4; ++mf) ldsm4(af[mf], (bb + aoff[mf]) ^ xm);
            #pragma unroll
            for (int p = 0; p < 4; ++p)   ldsm4(bf[p], (bb + boff[p]) ^ xm);
            #pragma unroll
            for (int mf = 0; mf < 4; ++mf)
                #pragma unroll
                for (int p = 0; p < 4; ++p) {
                    mma_f32(acc[mf][2 * p],     af[mf], bf[p][0], bf[p][2]);
                    mma_f32(acc[mf][2 * p + 1], af[mf], bf[p][1], bf[p][3]);
                }
        }
    }

    // fused epilogue: tanh(act + qb + pc*Wc) * Vw, reduce over this n-quarter
    #pragma unroll
    for (int mf = 0; mf < 4; ++mf) {
        const int rA = wm + mf * 16 + (lane >> 2);
        const float pA = pc_s[rA], pB = pc_s[rA + 8];
        float sA = 0.f, sB = 0.f;
        #pragma unroll
        for (int nf = 0; nf < 8; ++nf) {
            int c0 = wn + nf * 8 + 2 * (lane & 3);
            int c1 = c0 + 1;
            sA += tanhf(acc[mf][nf][0] + qb_s[c0] + pA * wc_s[c0]) * vw_s[c0];
            sA += tanhf(acc[mf][nf][1] + qb_s[c1] + pA * wc_s[c1]) * vw_s[c1];
            sB += tanhf(acc[mf][nf][2] + qb_s[c0] + pB * wc_s[c0]) * vw_s[c0];
            sB += tanhf(acc[mf][nf][3] + qb_s[c1] + pB * wc_s[c1]) * vw_s[c1];
        }
        sA += __shfl_xor_sync(0xffffffff, sA, 1);
        sA += __shfl_xor_sync(0xffffffff, sA, 2);
        sB += __shfl_xor_sync(0xffffffff, sB, 1);
        sB += __shfl_xor_sync(0xffffffff, sB, 2);
        if ((lane & 3) == 0) {
            Red[rA][wid & 3]     = sA;
            Red[rA + 8][wid & 3] = sB;
        }
    }
    __syncthreads();
    if (tid < 128) {
        g_spart[(size_t)nh * M_ + m0 + tid] =
            Red[tid][0] + Red[tid][1] + Red[tid][2] + Red[tid][3];
    }
}

// ============================================================================
// softmax over T per batch; writes attention_weights + coverage
// ============================================================================
__global__ void softmax_kernel(const float* __restrict__ prev_cov,
                               const float* __restrict__ Vb,
                               float* __restrict__ out) {
    __shared__ float sc[T_];
    __shared__ float red[256];
    const int b = blockIdx.x;
    const int tid = threadIdx.x;
    const float vb = Vb[0];

    float lmax = -1e30f;
    for (int t = tid; t < T_; t += 256) {
        size_t i = (size_t)b * T_ + t;
        float s = g_spart[i] + g_spart[M_ + i] + g_spart[2 * (size_t)M_ + i]
                + g_spart[3 * (size_t)M_ + i] + vb;
        sc[t] = s;
        lmax = fmaxf(lmax, s);
    }
    red[tid] = lmax;
    __syncthreads();
    for (int st = 128; st > 0; st >>= 1) {
        if (tid < st) red[tid] = fmaxf(red[tid], red[tid + st]);
        __syncthreads();
    }
    const float mx = red[0];
    __syncthreads();

    float lsum = 0.0f;
    for (int t = tid; t < T_; t += 256) {
        float e = expf(sc[t] - mx);
        sc[t] = e;
        lsum += e;
    }
    red[tid] = lsum;
    __syncthreads();
    for (int st = 128; st > 0; st >>= 1) {
        if (tid < st) red[tid] += red[tid + st];
        __syncthreads();
    }
    const float inv = 1.0f / red[0];

    float* aw_out  = out + B_ * D_;
    float* cov_out = out + B_ * D_ + B_ * T_;
    const float* pc = prev_cov + (size_t)b * T_;
    for (int t = tid; t < T_; t += 256) {
        float a = sc[t] * inv;
        aw_out[(size_t)b * T_ + t]  = a;
        cov_out[(size_t)b * T_ + t] = a + pc[t];
    }
}

// ============================================================================
// context: grid (32 chunks, 32 b), 256 threads; thread owns t = tid*8..tid*8+7
// (512B contiguous). Swizzle select (j>>1)&3 is COMPILE-TIME per unrolled j —
// no dynamic register indexing, no local spills, full MLP. Warp butterfly +
// smem combine -> FINAL context[b][c*32..c*32+31].
// ============================================================================
__global__ void ctx_kernel(const float* __restrict__ aw, float* __restrict__ out) {
    __shared__ float red[8][33];
    const int c = blockIdx.x, b = blockIdx.y;
    const int tid = threadIdx.x;
    const int w = tid >> 5, lane = tid & 31;

    // this thread's 8 consecutive t-blocks (each 64B = 4 uint4)
    const uint4* blk = (const uint4*)(g_va + ((size_t)c * M_ + (size_t)b * T_ + (size_t)tid * 8) * 32);
    const float* ap = aw + (size_t)b * T_ + (size_t)tid * 8;

    float a8[8];
    {
        float4 a0 = *(const float4*)(ap);
        float4 a1 = *(const float4*)(ap + 4);
        a8[0] = a0.x; a8[1] = a0.y; a8[2] = a0.z; a8[3] = a0.w;
        a8[4] = a1.x; a8[5] = a1.y; a8[6] = a1.z; a8[7] = a1.w;
    }

    float acc[32];
    #pragma unroll
    for (int e = 0; e < 32; ++e) acc[e] = 0.f;

    #pragma unroll
    for (int j = 0; j < 8; ++j) {
        const int swv = (j >> 1) & 3;            // compile-time per j
        const float a = a8[j];
        #pragma unroll
        for (int u = 0; u < 4; ++u) {
            uint4 raw = blk[j * 4 + (u ^ swv)];  // static index
            const __half2* hp = (const __half2*)&raw;
            #pragma unroll
            for (int q = 0; q < 4; ++q) {
                float2 f = __half22float2(hp[q]);
                acc[u * 8 + 2 * q]     = fmaf(a, f.x, acc[u * 8 + 2 * q]);
                acc[u * 8 + 2 * q + 1] = fmaf(a, f.y, acc[u * 8 + 2 * q + 1]);
            }
        }
    }

    // warp butterfly: all lanes end with warp-total for each e
    #pragma unroll
    for (int off = 16; off > 0; off >>= 1)
        #pragma unroll
        for (int e = 0; e < 32; ++e)
            acc[e] += __shfl_xor_sync(0xffffffff, acc[e], off);

    red[w][lane] = acc[lane];       // lane l stores element e=l of warp w
    __syncthreads();
    if (tid < 32) {
        float s = 0.f;
        #pragma unroll
        for (int ww = 0; ww < 8; ++ww) s += red[ww][tid];
        out[(size_t)b * D_ + c * 32 + tid] = s;
    }
}

// ============================================================================
extern "C" void kernel_launch(void* const* d_in, const int* in_sizes, int n_in,
                              void* d_out, int out_size) {
    const float* query    = (const float*)d_in[0];
    const float* values   = (const float*)d_in[1];
    const float* prev_cov = (const float*)d_in[2];
    const float* Wh       = (const float*)d_in[3];
    const float* bh       = (const float*)d_in[4];
    const float* Ws       = (const float*)d_in[5];
    const float* bs       = (const float*)d_in[6];
    const float* Wc       = (const float*)d_in[7];
    const float* bc       = (const float*)d_in[8];
    const float* Vw       = (const float*)d_in[9];
    const float* Vb       = (const float*)d_in[10];
    float* out = (float*)d_out;

    cudaFuncSetAttribute(score_gemm_kernel,
                         cudaFuncAttributeMaxDynamicSharedMemorySize, GEMM_SMEM);

    prep_kernel<<<NB_CV + NB_CW + NB_QP, 256>>>(values, Ws, query, Wh, bh, bs, bc);
    score_gemm_kernel<<<dim3(4, M_ / 128), 256, GEMM_SMEM>>>(prev_cov, Wc, Vw);
    softmax_kernel<<<B_, 256>>>(prev_cov, Vb, out);
    ctx_kernel<<<dim3(32, B_), 256>>>(out + B_ * D_, out);
}

// round 17
// speedup vs baseline: 1.0406x; 1.0317x over previous
#include <cuda_runtime.h>
#include <cuda_fp16.h>
#include <math.h>
#include <stdint.h>

#define B_  32
#define T_  2048
#define D_  1024
#define M_  (B_ * T_)
#define KS_  4

// ---------------- scratch (static device globals; no allocation) ----------------
// chunk-major, pre-swizzled: block (c, m) at (c*M_ + m)*32 halves (64B), inner
// 16B-unit u stored at position (u ^ ((m>>1)&3))&3.
__device__ __half g_va[(size_t)M_ * D_];     // 128 MB values fp16
__device__ __half g_wt[(size_t)D_ * D_];     // 2 MB  Ws^T fp16, same block layout (n)
__device__ float g_qpart[KS_ * B_ * D_];
__device__ float g_spart[4 * M_];            // per-n-quarter score partials

// ---------------- PTX helpers ----------------
__device__ __forceinline__ uint32_t smem_u32(const void* p) {
    uint32_t a;
    asm("{ .reg .u64 t; cvta.to.shared.u64 t, %1; cvt.u32.u64 %0, t; }" : "=r"(a) : "l"(p));
    return a;
}
__device__ __forceinline__ void ldsm4(uint32_t* r, uint32_t addr) {
    asm volatile("ldmatrix.sync.aligned.m8n8.x4.shared.b16 {%0,%1,%2,%3}, [%4];"
        : "=r"(r[0]), "=r"(r[1]), "=r"(r[2]), "=r"(r[3]) : "r"(addr));
}
__device__ __forceinline__ void mma_f32(float* d, const uint32_t* a, uint32_t b0, uint32_t b1) {
    asm("mma.sync.aligned.m16n8k16.row.col.f32.f16.f16.f32 "
        "{%0,%1,%2,%3}, {%4,%5,%6,%7}, {%8,%9}, {%0,%1,%2,%3};"
        : "+f"(d[0]), "+f"(d[1]), "+f"(d[2]), "+f"(d[3])
        : "r"(a[0]), "r"(a[1]), "r"(a[2]), "r"(a[3]), "r"(b0), "r"(b1));
}
#define MBAR_INIT(a, c) \
    asm volatile("mbarrier.init.shared.b64 [%0], %1;" :: "r"((uint32_t)(a)), "r"((uint32_t)(c)) : "memory")
#define MBAR_EXPECT_TX(a, n) \
    asm volatile("mbarrier.arrive.expect_tx.shared.b64 _, [%0], %1;" :: "r"((uint32_t)(a)), "r"((uint32_t)(n)) : "memory")
#define MBAR_WAIT(a, par) do { \
    uint32_t _m = (uint32_t)(a), _p = (uint32_t)(par), _d; \
    asm volatile("{\n\t.reg .pred p;\n\t" \
        "mbarrier.try_wait.parity.acquire.cta.shared::cta.b64 p, [%1], %2;\n\t" \
        "selp.b32 %0, 1, 0, p;\n\t}" : "=r"(_d) : "r"(_m), "r"(_p) : "memory"); \
    if (!_d) { \
        asm volatile("{\n\t.reg .pred P1;\n\t" \
            "WL_%=:\n\t" \
            "mbarrier.try_wait.parity.acquire.cta.shared::cta.b64 P1, [%0], %1, 0x989680;\n\t" \
            "@P1 bra.uni WD_%=;\n\t" \
            "bra.uni WL_%=;\n\t" \
            "WD_%=:\n\t}" :: "r"(_m), "r"(_p) : "memory"); \
    } \
} while (0)
__device__ __forceinline__ void bulk_cp(uint32_t dst, const void* src, uint32_t bytes, uint32_t mbar) {
    asm volatile("cp.async.bulk.shared::cta.global.mbarrier::complete_tx::bytes [%0], [%1], %2, [%3];"
        :: "r"(dst), "l"(src), "r"(bytes), "r"(mbar) : "memory");
}

// ============================================================================
// merged prep: conv_values (32768 blocks) | conv_ws (1024) | qproj (512)
// ============================================================================
#define NB_CV 32768
#define NB_CW 1024
#define NB_QP 512
__global__ void prep_kernel(const float* __restrict__ v,
                            const float* __restrict__ Ws,
                            const float* __restrict__ query,
                            const float* __restrict__ Wh,
                            const float* __restrict__ bh,
                            const float* __restrict__ bs,
                            const float* __restrict__ bc) {
    __shared__ float tile[32][33];
    const int bid = blockIdx.x;
    const int tid = threadIdx.x;

    if (bid < NB_CV) {
        // ---- conv_values: f32 [m][k] -> fp16 chunk-major pre-swizzled ----
        size_t t = (size_t)bid * 256 + tid;
        int u = (int)(t & 3);
        int m = (int)((t >> 2) & (M_ - 1));
        int c = (int)(t >> 18);
        const float4* src = (const float4*)(v + (size_t)m * D_ + c * 32 + u * 8);
        float4 x0 = src[0], x1 = src[1];
        __half h[8];
        h[0] = __float2half_rn(x0.x); h[1] = __float2half_rn(x0.y);
        h[2] = __float2half_rn(x0.z); h[3] = __float2half_rn(x0.w);
        h[4] = __float2half_rn(x1.x); h[5] = __float2half_rn(x1.y);
        h[6] = __float2half_rn(x1.z); h[7] = __float2half_rn(x1.w);
        int sw = (u ^ ((m >> 1) & 3)) & 3;
        *(uint4*)(g_va + ((size_t)c * M_ + m) * 32 + sw * 8) = *(uint4*)h;
    } else if (bid < NB_CV + NB_CW) {
        // ---- conv_ws: Ws [k][n] -> transposed fp16 chunk-major swizzled ----
        int cw = bid - NB_CV;
        const int n0 = (cw & 31) * 32, c = cw >> 5;
        const int tx = tid & 31, ty = tid >> 5;
        #pragma unroll
        for (int i = 0; i < 32; i += 8)
            tile[ty + i][tx] = Ws[(size_t)(c * 32 + ty + i) * D_ + n0 + tx];
        __syncthreads();
        if (tid < 128) {
            int nl = tid >> 2, u = tid & 3;
            __half h[8];
            #pragma unroll
            for (int j = 0; j < 8; ++j)
                h[j] = __float2half_rn(tile[u * 8 + j][nl]);
            int sw = (u ^ ((nl >> 1) & 3)) & 3;
            *(uint4*)(g_wt + ((size_t)c * D_ + n0 + nl) * 32 + sw * 8) = *(uint4*)h;
        }
    } else {
        // ---- qproj partials (k-split x4) ----
        int kbid = bid - NB_CV - NB_CW;
        int ks = kbid >> 7;
        int g  = (kbid & 127) * 256 + tid;
        int u = g & (D_ - 1);
        int b = g >> 10;
        float acc = (ks == 0) ? (bh[u] + bs[u] + bc[u]) : 0.0f;
        const float* q = query + (size_t)b * D_;
        int kbeg = ks * (D_ / KS_), kend = kbeg + D_ / KS_;
        #pragma unroll 8
        for (int k = kbeg; k < kend; ++k)
            acc = fmaf(q[k], Wh[(size_t)k * D_ + u], acc);
        g_qpart[(size_t)ks * B_ * D_ + g] = acc;
    }
}

// ============================================================================
// score GEMM: CTA = 128M x 256N quarter; grid (4 n-quarters, 512 m-blocks).
// 8 warps, warp tile 64x64. Pure fp16 HMMA, fp32 accumulate.
// smem fill via cp.async.bulk (A 8KB + B 16KB per chunk) + mbarrier.
// ============================================================================
#define BUF_B 24576                 // A 8K | B 16K
#define O_BH  8192
#define NSTAGE 3
#define MBAR_OFF (NSTAGE * BUF_B)   // 73728
#define EPI_OFF (MBAR_OFF + 64)
#define GEMM_SMEM (EPI_OFF + (256 * 3 + 128 + 512) * 4)

__global__ __launch_bounds__(256, 1)
void score_gemm_kernel(const float* __restrict__ prev_cov,
                       const float* __restrict__ Wc,
                       const float* __restrict__ Vw) {
    extern __shared__ char smem[];
    const uint32_t sb = smem_u32(smem);
    float* qb_s = (float*)(smem + EPI_OFF);          // 256
    float* wc_s = qb_s + 256;
    float* vw_s = qb_s + 512;
    float* pc_s = qb_s + 768;                        // 128
    float (*Red)[4] = (float(*)[4])(qb_s + 896);     // [128][4]

    const int tid  = threadIdx.x;
    const int wid  = tid >> 5;
    const int lane = tid & 31;
    const int wm   = (wid >> 2) * 64;                // 0 / 64
    const int wn   = (wid & 3) * 64;                 // 0..192

    const int nh  = blockIdx.x;                      // 0..3
    const int mb  = blockIdx.y;                      // 0..511
    const int m0  = mb * 128;
    const int b   = mb >> 4;
    const int tt0 = (mb & 15) * 128;

    if (tid == 0) {
        MBAR_INIT(sb + MBAR_OFF + 0,  1);
        MBAR_INIT(sb + MBAR_OFF + 8,  1);
        MBAR_INIT(sb + MBAR_OFF + 16, 1);
    }
    if (tid < 128) pc_s[tid] = prev_cov[(size_t)b * T_ + tt0 + tid];
    {
        int n = nh * 256 + tid;
        float q = g_qpart[(size_t)b * D_ + n]
                + g_qpart[(size_t)B_ * D_ + (size_t)b * D_ + n]
                + g_qpart[(size_t)2 * B_ * D_ + (size_t)b * D_ + n]
                + g_qpart[(size_t)3 * B_ * D_ + (size_t)b * D_ + n];
        qb_s[tid] = q;
        wc_s[tid] = Wc[n];
        vw_s[tid] = Vw[n];
    }
    __syncthreads();

    // ---- hoisted fragment addressing (kk=16 differs by ^0x20) ----
    const int lr  = (lane & 7) + (lane & 8);
    const uint32_t k8 = lane >> 4;                   // 0/1
    uint32_t aoff[4], boff[4];
    #pragma unroll
    for (int mf = 0; mf < 4; ++mf) {
        int r = wm + mf * 16 + lr;
        aoff[mf] = (uint32_t)(r << 6) + (((k8 ^ (r >> 1)) & 3) << 4);
    }
    #pragma unroll
    for (int p = 0; p < 4; ++p) {
        int n = wn + p * 16 + lr;
        boff[p] = (uint32_t)(n << 6) + (((k8 ^ (n >> 1)) & 3) << 4) + O_BH;
    }

    float acc[4][8][4];
    #pragma unroll
    for (int i = 0; i < 4; ++i)
        #pragma unroll
        for (int j = 0; j < 8; ++j)
            #pragma unroll
            for (int r = 0; r < 4; ++r) acc[i][j][r] = 0.0f;

    #define ISSUE_BULK(c) do {                                                 \
        if (tid == 0) {                                                        \
            int s_ = (c) % NSTAGE;                                             \
            uint32_t mb_ = sb + MBAR_OFF + s_ * 8;                             \
            uint32_t bb_ = sb + s_ * BUF_B;                                    \
            MBAR_EXPECT_TX(mb_, 24576u);                                       \
            bulk_cp(bb_,        g_va + ((size_t)(c) * M_ + m0) * 32,           \
                    8192u, mb_);                                               \
            bulk_cp(bb_ + O_BH, g_wt + ((size_t)(c) * D_ + nh * 256) * 32,     \
                    16384u, mb_);                                              \
        }                                                                      \
    } while (0)

    ISSUE_BULK(0);
    ISSUE_BULK(1);

    for (int c = 0; c < 32; ++c) {
        const int s = c % NSTAGE;
        MBAR_WAIT(sb + MBAR_OFF + s * 8, (uint32_t)((c / 3) & 1));
        __syncthreads();
        if (c + 2 < 32) ISSUE_BULK(c + 2);

        const uint32_t bb = sb + s * BUF_B;
        #pragma unroll
        for (int kk = 0; kk < 32; kk += 16) {
            const uint32_t xm = kk ? 0x20u : 0u;
            uint32_t af[4][4], bf[4][4];
            #pragma unroll
            for (int mf = 0; mf < 4; ++mf) ldsm4(af[mf], (bb + aoff[mf]) ^ xm);
            #pragma unroll
            for (int p = 0; p < 4; ++p)   ldsm4(bf[p], (bb + boff[p]) ^ xm);
            #pragma unroll
            for (int mf = 0; mf < 4; ++mf)
                #pragma unroll
                for (int p = 0; p < 4; ++p) {
                    mma_f32(acc[mf][2 * p],     af[mf], bf[p][0], bf[p][2]);
                    mma_f32(acc[mf][2 * p + 1], af[mf], bf[p][1], bf[p][3]);
                }
        }
    }

    // fused epilogue: tanh(act + qb + pc*Wc) * Vw, reduce over this n-quarter
    #pragma unroll
    for (int mf = 0; mf < 4; ++mf) {
        const int rA = wm + mf * 16 + (lane >> 2);
        const float pA = pc_s[rA], pB = pc_s[rA + 8];
        float sA = 0.f, sB = 0.f;
        #pragma unroll
        for (int nf = 0; nf < 8; ++nf) {
            int c0 = wn + nf * 8 + 2 * (lane & 3);
            int c1 = c0 + 1;
            sA += tanhf(acc[mf][nf][0] + qb_s[c0] + pA * wc_s[c0]) * vw_s[c0];
            sA += tanhf(acc[mf][nf][1] + qb_s[c1] + pA * wc_s[c1]) * vw_s[c1];
            sB += tanhf(acc[mf][nf][2] + qb_s[c0] + pB * wc_s[c0]) * vw_s[c0];
            sB += tanhf(acc[mf][nf][3] + qb_s[c1] + pB * wc_s[c1]) * vw_s[c1];
        }
        sA += __shfl_xor_sync(0xffffffff, sA, 1);
        sA += __shfl_xor_sync(0xffffffff, sA, 2);
        sB += __shfl_xor_sync(0xffffffff, sB, 1);
        sB += __shfl_xor_sync(0xffffffff, sB, 2);
        if ((lane & 3) == 0) {
            Red[rA][wid & 3]     = sA;
            Red[rA + 8][wid & 3] = sB;
        }
    }
    __syncthreads();
    if (tid < 128) {
        g_spart[(size_t)nh * M_ + m0 + tid] =
            Red[tid][0] + Red[tid][1] + Red[tid][2] + Red[tid][3];
    }
}

// ============================================================================
// softmax over T per batch; writes attention_weights + coverage
// ============================================================================
__global__ void softmax_kernel(const float* __restrict__ prev_cov,
                               const float* __restrict__ Vb,
                               float* __restrict__ out) {
    __shared__ float sc[T_];
    __shared__ float red[256];
    const int b = blockIdx.x;
    const int tid = threadIdx.x;
    const float vb = Vb[0];

    float lmax = -1e30f;
    for (int t = tid; t < T_; t += 256) {
        size_t i = (size_t)b * T_ + t;
        float s = g_spart[i] + g_spart[M_ + i] + g_spart[2 * (size_t)M_ + i]
                + g_spart[3 * (size_t)M_ + i] + vb;
        sc[t] = s;
        lmax = fmaxf(lmax, s);
    }
    red[tid] = lmax;
    __syncthreads();
    for (int st = 128; st > 0; st >>= 1) {
        if (tid < st) red[tid] = fmaxf(red[tid], red[tid + st]);
        __syncthreads();
    }
    const float mx = red[0];
    __syncthreads();

    float lsum = 0.0f;
    for (int t = tid; t < T_; t += 256) {
        float e = expf(sc[t] - mx);
        sc[t] = e;
        lsum += e;
    }
    red[tid] = lsum;
    __syncthreads();
    for (int st = 128; st > 0; st >>= 1) {
        if (tid < st) red[tid] += red[tid + st];
        __syncthreads();
    }
    const float inv = 1.0f / red[0];

    float* aw_out  = out + B_ * D_;
    float* cov_out = out + B_ * D_ + B_ * T_;
    const float* pc = prev_cov + (size_t)b * T_;
    for (int t = tid; t < T_; t += 256) {
        float a = sc[t] * inv;
        aw_out[(size_t)b * T_ + t]  = a;
        cov_out[(size_t)b * T_ + t] = a + pc[t];
    }
}

// ============================================================================
// context: grid (32 chunks, 32 b), 256 threads (8 warps).
// Lane-contiguous loads: warp reads 8 consecutive t-blocks (512B) per LDG.128
// (lane l -> physical unit l&3 of block t0 + (l>>2)) => 4 L1 wavefronts/load.
// Logical unit per lane is CONSTANT: u = (lane&3) ^ (lane>>3).
// Each lane accumulates 8 d-values; deterministic smem gather -> final out.
// ============================================================================
__global__ void ctx_kernel(const float* __restrict__ aw, float* __restrict__ out) {
    __shared__ float sa[T_];             // 8 KB
    __shared__ float red[8][32][8];      // 8 KB
    const int c = blockIdx.x, b = blockIdx.y;
    const int tid = threadIdx.x;
    const int w = tid >> 5, lane = tid & 31;

    #pragma unroll
    for (int i = 0; i < 8; ++i)
        sa[tid + 256 * i] = aw[(size_t)b * T_ + tid + 256 * i];
    __syncthreads();

    const int ts = lane >> 2;            // t-slot 0..7 within 8-block group
    const int up = lane & 3;             // physical 16B unit
    const __half* base = g_va + ((size_t)c * M_ + (size_t)b * T_) * 32;

    float acc[8];
    #pragma unroll
    for (int e = 0; e < 8; ++e) acc[e] = 0.f;

    #pragma unroll 4
    for (int it = 0; it < 32; ++it) {
        int t = it * 64 + w * 8 + ts;
        uint4 raw = *(const uint4*)(base + (size_t)t * 32 + up * 8);
        float a = sa[t];
        const __half2* hp = (const __half2*)&raw;
        #pragma unroll
        for (int q = 0; q < 4; ++q) {
            float2 f = __half22float2(hp[q]);
            acc[2 * q]     = fmaf(a, f.x, acc[2 * q]);
            acc[2 * q + 1] = fmaf(a, f.y, acc[2 * q + 1]);
        }
    }

    #pragma unroll
    for (int e = 0; e < 8; ++e) red[w][lane][e] = acc[e];
    __syncthreads();

    // 32 threads: thread tid = u*8+e gathers the 8 lanes with logical unit u
    // (lane = (u^bb) + (f<<2) + (bb<<3), bb 0..3, f 0..1) across 8 warps.
    if (tid < 32) {
        const int u = tid >> 3, e = tid & 7;
        float s = 0.f;
        #pragma unroll
        for (int w2 = 0; w2 < 8; ++w2)
            #pragma unroll
            for (int bb = 0; bb < 4; ++bb) {
                int l0 = (u ^ bb) + (bb << 3);
                s += red[w2][l0][e] + red[w2][l0 + 4][e];
            }
        out[(size_t)b * D_ + c * 32 + tid] = s;
    }
}

// ============================================================================
extern "C" void kernel_launch(void* const* d_in, const int* in_sizes, int n_in,
                              void* d_out, int out_size) {
    const float* query    = (const float*)d_in[0];
    const float* values   = (const float*)d_in[1];
    const float* prev_cov = (const float*)d_in[2];
    const float* Wh       = (const float*)d_in[3];
    const float* bh       = (const float*)d_in[4];
    const float* Ws       = (const float*)d_in[5];
    const float* bs       = (const float*)d_in[6];
    const float* Wc       = (const float*)d_in[7];
    const float* bc       = (const float*)d_in[8];
    const float* Vw       = (const float*)d_in[9];
    const float* Vb       = (const float*)d_in[10];
    float* out = (float*)d_out;

    cudaFuncSetAttribute(score_gemm_kernel,
                         cudaFuncAttributeMaxDynamicSharedMemorySize, GEMM_SMEM);

    prep_kernel<<<NB_CV + NB_CW + NB_QP, 256>>>(values, Ws, query, Wh, bh, bs, bc);
    score_gemm_kernel<<<dim3(4, M_ / 128), 256, GEMM_SMEM>>>(prev_cov, Wc, Vw);
    softmax_kernel<<<B_, 256>>>(prev_cov, Vb, out);
    ctx_kernel<<<dim3(32, B_), 256>>>(out + B_ * D_, out);
}